// round 17
// baseline (speedup 1.0000x reference)
#include <cuda_runtime.h>

// SSIM loss, fused single pass. (u,v)=(p+t,p-t) rotation, f32x2 packed.
// Warp-private row tiles (64 cols + 6-col halos), NO CTA barrier in mainloop.
// PHASE-SPECIALIZED: checked warmup (5 pairs) -> branch-free steady chunks
// (11 pairs, all guards constant-folded) -> checked fallback chunks.
// NT=256, 2 cols/thread, 6 strips -> grid 288 -> 2 CTAs/SM.
// UV ring in registers (static slots); Q ring in smem (thread-private).
// pred/target: (16,3,512,512) fp32 -> out: 16 fp32 (1 - mean ssim per sample).

#define WIDTH   512
#define HEIGHT  512
#define PADR    5
#define NT      256
#define NSTRIP  6
#define STRIPH  86
#define WRS     80
#define NBLOCKS (48 * NSTRIP)

#define OF_Q    0              // 11*256*16 = 45056
#define OF_ROW  45056          // 4 sets * 8 warps * 80 * 8 = 20480
#define OF_RED  65536          // 256*4
#define SMEM_SZ 66560

#define K1f 1.4641f
#define K2f 13.1769f

typedef unsigned long long u64;

__device__ float g_partials[NBLOCKS];
__device__ unsigned int g_count;

__device__ __forceinline__ u64 pk2(float a, float b) {
    u64 r; asm("mov.b64 %0,{%1,%2};" : "=l"(r) : "f"(a), "f"(b)); return r;
}
__device__ __forceinline__ float2 up2(u64 a) {
    float2 r; asm("mov.b64 {%0,%1},%2;" : "=f"(r.x), "=f"(r.y) : "l"(a)); return r;
}
__device__ __forceinline__ u64 add2(u64 a, u64 b) {
    u64 r; asm("add.rn.f32x2 %0,%1,%2;" : "=l"(r) : "l"(a), "l"(b)); return r;
}
__device__ __forceinline__ u64 mul2(u64 a, u64 b) {
    u64 r; asm("mul.rn.f32x2 %0,%1,%2;" : "=l"(r) : "l"(a), "l"(b)); return r;
}
__device__ __forceinline__ u64 fma2(u64 a, u64 b, u64 c) {
    u64 r; asm("fma.rn.f32x2 %0,%1,%2,%3;" : "=l"(r) : "l"(a), "l"(b), "l"(c)); return r;
}
__device__ __forceinline__ float rcpa(float x) {
    float r; asm("rcp.approx.f32 %0,%1;" : "=f"(r) : "f"(x)); return r;
}

// Horizontal 11-tap windows for 2 output cols, tree-structured; all LDS.128.
__device__ __forceinline__ void hwin2(const float2* __restrict__ row, int xb,
                                      u64 own0, u64 own1,
                                      u64 hUV[2], u64 hQ[2])
{
    ulonglong2 L0 = *(const ulonglong2*)(row + xb + 2);    // xb+2 (dead), xb+3
    ulonglong2 L1 = *(const ulonglong2*)(row + xb + 4);
    ulonglong2 L2 = *(const ulonglong2*)(row + xb + 6);
    ulonglong2 L3 = *(const ulonglong2*)(row + xb + 10);
    ulonglong2 L4 = *(const ulonglong2*)(row + xb + 12);
    ulonglong2 L5 = *(const ulonglong2*)(row + xb + 14);   // xb+14, xb+15 (dead)
    const u64 T0  = L0.y;
    const u64 T11 = L5.x;

    u64 c1 = add2(add2(L1.x, L1.y), add2(L2.x, L2.y));
    c1 = add2(c1, own0);
    u64 c2 = add2(add2(own1, L3.x), add2(L3.y, L4.x));
    c2 = add2(c2, L4.y);
    u64 mid = add2(c1, c2);
    hUV[0] = add2(mid, T0);
    hUV[1] = add2(mid, T11);

    u64 q1 = fma2(L1.y, L1.y, mul2(L1.x, L1.x));
    q1 = fma2(L2.x, L2.x, q1);
    q1 = fma2(L2.y, L2.y, q1);
    q1 = fma2(own0, own0, q1);
    u64 q2 = fma2(L3.x, L3.x, mul2(own1, own1));
    q2 = fma2(L3.y, L3.y, q2);
    q2 = fma2(L4.x, L4.x, q2);
    q2 = fma2(L4.y, L4.y, q2);
    u64 midq = add2(q1, q2);
    hQ[0] = fma2(T0, T0, midq);
    hQ[1] = fma2(T11, T11, midq);
}

// SSIM emit for 2 columns; one rcp serves both divides.
__device__ __forceinline__ void emit2(const u64 SUV[2], const u64 SQ2[2], float& acc)
{
    float n[2], d[2];
#pragma unroll
    for (int c = 0; c < 2; c++) {
        float2 qf = up2(SQ2[c]);
        float2 s2 = up2(mul2(SUV[c], SUV[c]));
        float A = s2.x - s2.y;
        float B = s2.x + s2.y;
        float qd = qf.x - qf.y;
        float qs = qf.x + qf.y;
        float a  = fmaf(0.5f, A, K1f);
        float b  = fmaf(60.5f, qd, fmaf(-0.5f, A, K2f));
        n[c] = a * b;
        float d1 = fmaf(0.5f, B, K1f);
        float d2 = fmaf(60.5f, qs, fmaf(-0.5f, B, K2f));
        d[c] = d1 * d2;
    }
    float r = rcpa(d[0] * d[1]);
    acc += __saturatef(n[0] * r * d[1]) + __saturatef(n[1] * r * d[0]);
}

// Process one row pair. CHK=0: all guards fold away (steady-state fast path).
#define PAIR_BODY(BASE, SA, SB, PH, CHK) do {                                  \
    const int base_ = (BASE);                                                  \
    float2* rA = rowbuf + (((PH) * 2 + 0) * 8 + w) * WRS;                      \
    float2* rB = rowbuf + (((PH) * 2 + 1) * 8 + w) * WRS;                      \
    const bool vA = !(CHK) || ((base_ >= 0) && (base_ < HEIGHT));              \
    const bool vB = !(CHK) || ((base_ + 1 >= 0) && (base_ + 1 < HEIGHT));      \
    u64 oA0, oA1, oB0, oB1;                                                    \
    {                                                                          \
        float4 wo = make_float4(0.f, 0.f, 0.f, 0.f);                           \
        if (vA) wo = make_float4(cp0.x + ct0.x, cp0.x - ct0.x,                 \
                                 cp0.y + ct0.y, cp0.y - ct0.y);                \
        oA0 = pk2(wo.x, wo.y); oA1 = pk2(wo.z, wo.w);                          \
        *(float4*)(rA + xb + 8) = wo;                                          \
        if (l < 6) {                                                           \
            float4 wh = make_float4(0.f, 0.f, 0.f, 0.f);                       \
            if (vA && hv) wh = make_float4(hp0.x + ht0.x, hp0.x - ht0.x,       \
                                           hp0.y + ht0.y, hp0.y - ht0.y);      \
            *(float4*)(rA + hbuf) = wh;                                        \
        }                                                                      \
        wo = make_float4(0.f, 0.f, 0.f, 0.f);                                  \
        if (vB) wo = make_float4(cp1.x + ct1.x, cp1.x - ct1.x,                 \
                                 cp1.y + ct1.y, cp1.y - ct1.y);                \
        oB0 = pk2(wo.x, wo.y); oB1 = pk2(wo.z, wo.w);                          \
        *(float4*)(rB + xb + 8) = wo;                                          \
        if (l < 6) {                                                           \
            float4 wh = make_float4(0.f, 0.f, 0.f, 0.f);                       \
            if (vB && hv) wh = make_float4(hp1.x + ht1.x, hp1.x - ht1.x,       \
                                           hp1.y + ht1.y, hp1.y - ht1.y);      \
            *(float4*)(rB + hbuf) = wh;                                        \
        }                                                                      \
    }                                                                          \
    {                                                                          \
        const int yn0 = base_ + 2, yn1 = base_ + 3;                            \
        if (!(CHK) || (yn0 >= 0 && yn0 < HEIGHT)) {                            \
            cp0 = *(const float2*)(P + (size_t)yn0 * WIDTH + x0g);             \
            ct0 = *(const float2*)(T + (size_t)yn0 * WIDTH + x0g);             \
            if (hv) {                                                          \
                hp0 = *(const float2*)(P + (size_t)yn0 * WIDTH + hcol);        \
                ht0 = *(const float2*)(T + (size_t)yn0 * WIDTH + hcol);        \
            }                                                                  \
        }                                                                      \
        if (!(CHK) || (yn1 >= 0 && yn1 < HEIGHT)) {                            \
            cp1 = *(const float2*)(P + (size_t)yn1 * WIDTH + x0g);             \
            ct1 = *(const float2*)(T + (size_t)yn1 * WIDTH + x0g);             \
            if (hv) {                                                          \
                hp1 = *(const float2*)(P + (size_t)yn1 * WIDTH + hcol);        \
                ht1 = *(const float2*)(T + (size_t)yn1 * WIDTH + hcol);        \
            }                                                                  \
        }                                                                      \
    }                                                                          \
    __syncwarp();                                                              \
    {                                                                          \
        u64 hUV[2], hQ[2];                                                     \
        hwin2(rA, xb, oA0, oA1, hUV, hQ);                                      \
        {                                                                      \
            ulonglong2 q = qring[(SA) * NT];                                   \
            SUV[0] = add2(SUV[0], fma2(rUV[(SA)][0], M1, hUV[0]));             \
            SUV[1] = add2(SUV[1], fma2(rUV[(SA)][1], M1, hUV[1]));             \
            SQ2[0] = add2(SQ2[0], fma2(q.x, M1, hQ[0]));                       \
            SQ2[1] = add2(SQ2[1], fma2(q.y, M1, hQ[1]));                       \
            rUV[(SA)][0] = hUV[0]; rUV[(SA)][1] = hUV[1];                      \
            qring[(SA) * NT] = make_ulonglong2(hQ[0], hQ[1]);                  \
        }                                                                      \
        if (!(CHK) || (base_ >= emit0)) emit2(SUV, SQ2, acc);                  \
        hwin2(rB, xb, oB0, oB1, hUV, hQ);                                      \
        {                                                                      \
            ulonglong2 q = qring[(SB) * NT];                                   \
            SUV[0] = add2(SUV[0], fma2(rUV[(SB)][0], M1, hUV[0]));             \
            SUV[1] = add2(SUV[1], fma2(rUV[(SB)][1], M1, hUV[1]));             \
            SQ2[0] = add2(SQ2[0], fma2(q.x, M1, hQ[0]));                       \
            SQ2[1] = add2(SQ2[1], fma2(q.y, M1, hQ[1]));                       \
            rUV[(SB)][0] = hUV[0]; rUV[(SB)][1] = hUV[1];                      \
            qring[(SB) * NT] = make_ulonglong2(hQ[0], hQ[1]);                  \
        }                                                                      \
        if (!(CHK) || (base_ + 1 >= emit0 && base_ + 1 < yend))                \
            emit2(SUV, SQ2, acc);                                              \
    }                                                                          \
} while (0)

__global__ __launch_bounds__(NT, 2)
void ssim_main_kernel(const float* __restrict__ pred, const float* __restrict__ targ,
                      float* __restrict__ out)
{
    extern __shared__ char sm[];
    float2* rowbuf = (float2*)(sm + OF_ROW);   // [4 sets][8 warps][WRS]
    float*  red    = (float*)(sm + OF_RED);
    __shared__ int s_last;

    const int tid   = threadIdx.x;
    const int w     = tid >> 5;
    const int l     = tid & 31;
    const int bid   = blockIdx.x;
    const int img   = bid / NSTRIP;
    const int strip = bid - img * NSTRIP;
    const int r0    = strip * STRIPH;
    const int r1    = min(HEIGHT, r0 + STRIPH);
    const int yend  = r1 + PADR;
    const int emit0 = r0 + PADR;
    const int start = r0 - PADR;

    const float* __restrict__ P = pred + (size_t)img * (WIDTH * HEIGHT);
    const float* __restrict__ T = targ + (size_t)img * (WIDTH * HEIGHT);
    const int x0g = 64 * w + 2 * l;
    const int xb  = 2 * l;

    const int  hcol = (l < 3) ? (64 * w - 6 + 2 * l) : (64 * w + 64 + 2 * (l - 3));
    const int  hbuf = (l < 3) ? (2 + 2 * l) : (72 + 2 * (l - 3));
    const bool hv   = (l < 6) && (hcol >= 0) && (hcol < WIDTH);

    const u64 M1 = pk2(-1.f, -1.f);

    u64 rUV[11][2];
#pragma unroll
    for (int s = 0; s < 11; s++) { rUV[s][0] = 0; rUV[s][1] = 0; }

    ulonglong2* qring = (ulonglong2*)(sm + OF_Q) + tid;
    {
        ulonglong2 z2 = make_ulonglong2(0ull, 0ull);
#pragma unroll
        for (int s = 0; s < 11; s++) qring[s * NT] = z2;
    }

    u64 SUV[2] = {0, 0}, SQ2[2] = {0, 0};
    float acc = 0.f;

    // prefetch rows start, start+1 (own + halo)
    float2 cp0 = {}, ct0 = {}, cp1 = {}, ct1 = {};
    float2 hp0 = {}, ht0 = {}, hp1 = {}, ht1 = {};
    if (start >= 0) {
        cp0 = *(const float2*)(P + (size_t)start * WIDTH + x0g);
        ct0 = *(const float2*)(T + (size_t)start * WIDTH + x0g);
        if (hv) {
            hp0 = *(const float2*)(P + (size_t)start * WIDTH + hcol);
            ht0 = *(const float2*)(T + (size_t)start * WIDTH + hcol);
        }
    }
    if (start + 1 >= 0) {
        cp1 = *(const float2*)(P + (size_t)(start + 1) * WIDTH + x0g);
        ct1 = *(const float2*)(T + (size_t)(start + 1) * WIDTH + x0g);
        if (hv) {
            hp1 = *(const float2*)(P + (size_t)(start + 1) * WIDTH + hcol);
            ht1 = *(const float2*)(T + (size_t)(start + 1) * WIDTH + hcol);
        }
    }

    // ---- Phase A: checked warmup, 5 pairs (10 rows), slots 0..9, no emits ----
#pragma unroll
    for (int wp = 0; wp < 5; wp++)
        PAIR_BODY(start + 2 * wp, 2 * wp, 2 * wp + 1, (wp & 1), 1);

    int bc = start + 10;     // == emit0; next slot is 10
    int kp = 1;              // pair parity after 5 warmup pairs

    // ---- Phase B: branch-free steady chunks (11 pairs = 22 rows) ----
    // Safe iff last pair base bc+20 satisfies: +3 prefetch < HEIGHT, +1 < yend.
    const int lim_full = min(HEIGHT - 24, yend - 22);
    while (bc <= lim_full) {
#pragma unroll
        for (int p = 0; p < 11; p++)
            PAIR_BODY(bc + 2 * p, (10 + 2 * p) % 11, (11 + 2 * p) % 11,
                      (kp ^ (p & 1)), 0);
        bc += 22; kp ^= 1;
    }

    // ---- Phase C: checked fallback chunks (tail) ----
    while (bc < yend) {
#pragma unroll
        for (int p = 0; p < 11; p++) {
            const int base = bc + 2 * p;
            if (base < yend)
                PAIR_BODY(base, (10 + 2 * p) % 11, (11 + 2 * p) % 11,
                          (kp ^ (p & 1)), 1);
        }
        bc += 22; kp ^= 1;
    }

    // deterministic block reduction
    red[tid] = acc;
    __syncthreads();
#pragma unroll
    for (int s = NT / 2; s > 0; s >>= 1) {
        if (tid < s) red[tid] += red[tid + s];
        __syncthreads();
    }
    if (tid == 0) {
        g_partials[bid] = red[0];
        __threadfence();
        unsigned int c = atomicAdd(&g_count, 1);
        s_last = (c == NBLOCKS - 1);
    }
    __syncthreads();
    if (s_last) {
        if (tid < 16) {
            float s = 0.f;
#pragma unroll
            for (int j = 0; j < 3 * NSTRIP; j++)
                s += __ldcg(&g_partials[tid * (3 * NSTRIP) + j]);
            out[tid] = 1.f - s * (1.f / (3.f * 512.f * 512.f));
        }
        if (tid == 0) g_count = 0;   // reset for next graph replay
    }
}

extern "C" void kernel_launch(void* const* d_in, const int* in_sizes, int n_in,
                              void* d_out, int out_size) {
    const float* pred = (const float*)d_in[0];
    const float* targ = (const float*)d_in[1];
    cudaFuncSetAttribute(ssim_main_kernel,
                         cudaFuncAttributeMaxDynamicSharedMemorySize, SMEM_SZ);
    ssim_main_kernel<<<NBLOCKS, NT, SMEM_SZ>>>(pred, targ, (float*)d_out);
}